// round 2
// baseline (speedup 1.0000x reference)
#include <cuda_runtime.h>
#include <math.h>

#define Bb 64
#define Ss 256
#define Vv 32000
#define Ee 1024
#define Hh 1024
#define N4 4096          // 4 gates * H
#define NSPLIT 4
#define KCH (Hh / NSPLIT)

// Scratch (static device globals — no allocations allowed)
__device__ float g_xproj[67108864UL];        // [S, B, 4*H] = 256*64*4096 fp32 (256 MiB)
__device__ float g_h[Bb * Hh];
__device__ float g_c[Bb * Hh];
__device__ float g_part[NSPLIT * Bb * N4];   // split-K partial sums (4 MiB)

// ---------------------------------------------------------------------------
__global__ void init_kernel() {
    int idx = blockIdx.x * blockDim.x + threadIdx.x;
    if (idx < Bb * Hh) { g_h[idx] = 0.f; g_c[idx] = 0.f; }
}

// ---------------------------------------------------------------------------
// xproj[s,b,g,h] = sum_e C[X[b,s],e] * Wx[g,e,h] + bx[g,h] + bg[g,h]
// GEMM: M = S*B = 16384 (m = s*64+b), N = 4096 (n = g*1024+h), K = E = 1024.
// 128x128 block tile, 256 threads, 8x8 per-thread tile, K-chunk 8.
__global__ __launch_bounds__(256) void xproj_kernel(
    const int* __restrict__ X, const float* __restrict__ C,
    const float* __restrict__ Wx, const float* __restrict__ bx,
    const float* __restrict__ bg)
{
    __shared__ float As[8][128];
    __shared__ float Bs[8][128];
    __shared__ int tok_s[128];

    const int bm = blockIdx.y << 7;
    const int bn = blockIdx.x << 7;
    const int gate = bn >> 10;
    const int h0 = bn & 1023;
    const float* __restrict__ Wg = Wx + (size_t)gate * Ee * Hh;
    const int tid = threadIdx.x;

    if (tid < 128) {
        int mg = bm + tid;                       // m = s*64 + b
        tok_s[tid] = X[(mg & 63) * Ss + (mg >> 6)];
    }
    __syncthreads();

    const int tm = (tid >> 4) << 3;
    const int tn = (tid & 15) << 3;
    const int am = tid >> 1;          // 0..127
    const int ak = (tid & 1) << 2;    // 0 or 4
    const int bk = tid >> 5;          // 0..7
    const int bnl = (tid & 31) << 2;  // 0..124

    float acc[8][8];
#pragma unroll
    for (int i = 0; i < 8; i++)
#pragma unroll
        for (int j = 0; j < 8; j++) acc[i][j] = 0.f;

    const float* __restrict__ aptr = C + (size_t)tok_s[am] * Ee + ak;

    for (int k0 = 0; k0 < Ee; k0 += 8) {
        float4 av = *(const float4*)(aptr + k0);
        float4 bv = *(const float4*)(Wg + (size_t)(k0 + bk) * Hh + h0 + bnl);
        __syncthreads();
        As[ak + 0][am] = av.x;
        As[ak + 1][am] = av.y;
        As[ak + 2][am] = av.z;
        As[ak + 3][am] = av.w;
        *(float4*)(&Bs[bk][bnl]) = bv;
        __syncthreads();
#pragma unroll
        for (int kk = 0; kk < 8; kk++) {
            float a[8], b[8];
            *(float4*)(a)     = *(const float4*)(&As[kk][tm]);
            *(float4*)(a + 4) = *(const float4*)(&As[kk][tm + 4]);
            *(float4*)(b)     = *(const float4*)(&Bs[kk][tn]);
            *(float4*)(b + 4) = *(const float4*)(&Bs[kk][tn + 4]);
#pragma unroll
            for (int i = 0; i < 8; i++)
#pragma unroll
                for (int j = 0; j < 8; j++)
                    acc[i][j] = fmaf(a[i], b[j], acc[i][j]);
        }
    }

#pragma unroll
    for (int i = 0; i < 8; i++) {
        size_t ro = (size_t)(bm + tm + i) * N4;
#pragma unroll
        for (int j = 0; j < 8; j++) {
            int n = bn + tn + j;
            g_xproj[ro + n] = acc[i][j] + bx[n] + bg[n];
        }
    }
}

// ---------------------------------------------------------------------------
// Per-step partial GEMM: part[split][b][n] = sum_{k in chunk} h[b,k] * Wh[g,k,hcol]
// M = 64 (all batch), N-tile = 128, K-chunk per block = 256 (NSPLIT=4) -> 128 blocks.
__global__ __launch_bounds__(256) void step_gemm(const float* __restrict__ Wh)
{
    __shared__ float As[16][64];
    __shared__ float Bs[16][128];

    const int bn = blockIdx.x << 7;        // 0..4095
    const int split = blockIdx.y;          // 0..NSPLIT-1
    const int kbase = split * KCH;
    const int gate = bn >> 10;
    const int h0 = bn & 1023;
    const float* __restrict__ Wg = Wh + (size_t)gate * Hh * Hh;
    const int tid = threadIdx.x;

    const int tm = (tid >> 4) << 2;   // 0..60
    const int tn = (tid & 15) << 3;   // 0..120
    const int am = tid >> 2;          // 0..63
    const int ak = (tid & 3) << 2;    // 0..12
    const int bk = tid >> 4;          // 0..15
    const int bnl = (tid & 15) << 3;  // 0..120

    float acc[4][8];
#pragma unroll
    for (int i = 0; i < 4; i++)
#pragma unroll
        for (int j = 0; j < 8; j++) acc[i][j] = 0.f;

    for (int k0 = 0; k0 < KCH; k0 += 16) {
        float4 av = *(const float4*)(g_h + am * Hh + kbase + k0 + ak);
        const float* wrow = Wg + (size_t)(kbase + k0 + bk) * Hh + h0 + bnl;
        float4 bv0 = *(const float4*)(wrow);
        float4 bv1 = *(const float4*)(wrow + 4);
        __syncthreads();
        As[ak + 0][am] = av.x;
        As[ak + 1][am] = av.y;
        As[ak + 2][am] = av.z;
        As[ak + 3][am] = av.w;
        *(float4*)(&Bs[bk][bnl])     = bv0;
        *(float4*)(&Bs[bk][bnl + 4]) = bv1;
        __syncthreads();
#pragma unroll
        for (int kk = 0; kk < 16; kk++) {
            float a[4], b[8];
            *(float4*)(a)     = *(const float4*)(&As[kk][tm]);
            *(float4*)(b)     = *(const float4*)(&Bs[kk][tn]);
            *(float4*)(b + 4) = *(const float4*)(&Bs[kk][tn + 4]);
#pragma unroll
            for (int i = 0; i < 4; i++)
#pragma unroll
                for (int j = 0; j < 8; j++)
                    acc[i][j] = fmaf(a[i], b[j], acc[i][j]);
        }
    }

#pragma unroll
    for (int i = 0; i < 4; i++) {
        size_t ro = ((size_t)split * Bb + (tm + i)) * N4 + bn + tn;
#pragma unroll
        for (int j = 0; j < 8; j++)
            g_part[ro + j] = acc[i][j];
    }
}

// ---------------------------------------------------------------------------
// Reduce split-K partials + xproj + bh, apply LSTM cell, update h/c in place.
__global__ void step_act(const float* __restrict__ bh, int t)
{
    int idx = blockIdx.x * blockDim.x + threadIdx.x;  // 0..B*H-1
    int b = idx >> 10;
    int k = idx & 1023;
    const float* __restrict__ xp = g_xproj + ((size_t)t * Bb + b) * N4;

    float g[4];
#pragma unroll
    for (int gg = 0; gg < 4; gg++) {
        int n = gg * Hh + k;
        float s = xp[n] + bh[n];
#pragma unroll
        for (int p = 0; p < NSPLIT; p++)
            s += g_part[((size_t)p * Bb + b) * N4 + n];
        g[gg] = s;
    }
    float vi = 1.f / (1.f + expf(-g[0]));
    float vf = 1.f / (1.f + expf(-g[1]));
    float vo = 1.f / (1.f + expf(-g[2]));
    float c  = vf * g_c[idx] + vi * tanhf(g[3]);
    g_c[idx] = c;
    g_h[idx] = vo * tanhf(c);
}

// ---------------------------------------------------------------------------
// out[b, v] = sum_k h[b,k] * Wout[k,v] + bout[v].  M=64, N=32000, K=1024.
// N-tile 128 -> 250 blocks, full K.
__global__ __launch_bounds__(256) void out_kernel(
    const float* __restrict__ Wout, const float* __restrict__ bout,
    float* __restrict__ out)
{
    __shared__ float As[16][64];
    __shared__ float Bs[16][128];

    const int bn = blockIdx.x << 7;  // 0..31872
    const int tid = threadIdx.x;

    const int tm = (tid >> 4) << 2;
    const int tn = (tid & 15) << 3;
    const int am = tid >> 2;
    const int ak = (tid & 3) << 2;
    const int bk = tid >> 4;
    const int bnl = (tid & 15) << 3;

    float acc[4][8];
#pragma unroll
    for (int i = 0; i < 4; i++)
#pragma unroll
        for (int j = 0; j < 8; j++) acc[i][j] = 0.f;

    for (int k0 = 0; k0 < Hh; k0 += 16) {
        float4 av = *(const float4*)(g_h + am * Hh + k0 + ak);
        const float* wrow = Wout + (size_t)(k0 + bk) * Vv + bn + bnl;
        float4 bv0 = *(const float4*)(wrow);
        float4 bv1 = *(const float4*)(wrow + 4);
        __syncthreads();
        As[ak + 0][am] = av.x;
        As[ak + 1][am] = av.y;
        As[ak + 2][am] = av.z;
        As[ak + 3][am] = av.w;
        *(float4*)(&Bs[bk][bnl])     = bv0;
        *(float4*)(&Bs[bk][bnl + 4]) = bv1;
        __syncthreads();
#pragma unroll
        for (int kk = 0; kk < 16; kk++) {
            float a[4], b[8];
            *(float4*)(a)     = *(const float4*)(&As[kk][tm]);
            *(float4*)(b)     = *(const float4*)(&Bs[kk][tn]);
            *(float4*)(b + 4) = *(const float4*)(&Bs[kk][tn + 4]);
#pragma unroll
            for (int i = 0; i < 4; i++)
#pragma unroll
                for (int j = 0; j < 8; j++)
                    acc[i][j] = fmaf(a[i], b[j], acc[i][j]);
        }
    }

#pragma unroll
    for (int i = 0; i < 4; i++) {
        size_t ro = (size_t)(tm + i) * Vv + bn + tn;
#pragma unroll
        for (int j = 0; j < 8; j++)
            out[ro + j] = acc[i][j] + bout[bn + tn + j];
    }
}

// ---------------------------------------------------------------------------
extern "C" void kernel_launch(void* const* d_in, const int* in_sizes, int n_in,
                              void* d_out, int out_size)
{
    const int*   X    = (const int*)d_in[0];
    const float* C    = (const float*)d_in[1];
    const float* Wx   = (const float*)d_in[2];
    const float* bx   = (const float*)d_in[3];
    const float* Wh   = (const float*)d_in[4];
    const float* bh   = (const float*)d_in[5];
    const float* bg   = (const float*)d_in[6];
    const float* Wout = (const float*)d_in[7];
    const float* bout = (const float*)d_in[8];
    float* out = (float*)d_out;

    init_kernel<<<(Bb * Hh + 255) / 256, 256>>>();
    xproj_kernel<<<dim3(N4 / 128, (Ss * Bb) / 128), 256>>>(X, C, Wx, bx, bg);

    for (int t = 0; t < Ss; t++) {
        step_gemm<<<dim3(N4 / 128, NSPLIT), 256>>>(Wh);
        step_act<<<(Bb * Hh + 255) / 256, 256>>>(bh, t);
    }

    out_kernel<<<Vv / 128, 256>>>(Wout, bout, out);
}